// round 12
// baseline (speedup 1.0000x reference)
#include <cuda_runtime.h>
#include <cuda_bf16.h>
#include <cstdint>

// Inputs (metadata order):
//   d_in[0] = z          float32 [12288, 128]
//   d_in[1] = edge_index int32 [2, 393216] (jnp.int64 silently downcast; detect)
//   d_in[2] = edge_attr  float32 [393216, 4]
//   d_in[3] = W          float32 [1, 256]
//   d_in[4] = b          float32 [1]
// Output: float32 [12288, 12288]
//
// out[r,c] = sum_dup(attr_sum) + (u[r]+v[c]+b) once per distinct cell.
// Single mega kernel, block partition [UV | EDGE | ZERO]:
//   UV:   per-node dots u/v, release g_uv_done.
//   EDGE: hash-insert (atomicCAS election) + atomicAdd; the elected inserter
//         appends its hash slot to the per-SEGMENT list of the target cell;
//         block signals g_edge_done when finished.
//   ZERO: block b owns contiguous segment b (32768 cells = 128KB): zero it,
//         wait edge_done (no-op: zeros launch after edges exit), then plain-
//         store its segment's hash entries into the L2-hot segment and clear
//         those slots. Scatter thus rides inside the zero wave.
// Dependency chain UV <- EDGE <- ZERO matches dispatch order => deadlock-free.
// Tail kernel: safety sweep for CAP-overflow slots (none in practice) +
// flag re-arm. All scratch self-cleaning => graph-replay deterministic.

#define N_NODES 12288
#define N_EDGES 393216

#define UV_BLOCKS    1536   // 8 warps/block -> 12288 warps, one per node
#define EDGE_BLOCKS  1536   // thread per edge
#define NSEG         4608   // 151M cells / 32768
#define SEG_SHIFT    15     // 32768 cells per segment
#define SEG_F4       8192   // float4 per segment (128KB)
#define SEG_CAP      512    // list capacity (expected ~85/seg)

#define HASH_BITS 20
#define HASH_SIZE (1u << HASH_BITS)
#define HASH_MASK (HASH_SIZE - 1u)

__device__ int      g_keys[HASH_SIZE];          // cell+1, 0 = empty; zero-init
__device__ float    g_vals[HASH_SIZE];          // accumulated value; zero-init
__device__ float    g_u[N_NODES];
__device__ float    g_v[N_NODES];
__device__ unsigned g_uv_done;                  // zero-init
__device__ unsigned g_edge_done;                // zero-init
__device__ unsigned g_seg_cnt[NSEG];            // zero-init
__device__ unsigned g_seg_list[NSEG * SEG_CAP]; // hash-slot ids per segment

// ---------------------------------------------------------------------------
__device__ __forceinline__ int block_detect_is64(const int* __restrict__ ei32,
                                                 int* sh_flag) {
    if (threadIdx.x < 32) {
        int w = ei32[2 * threadIdx.x + 1];
        unsigned any = __ballot_sync(0xFFFFFFFFu, w != 0);
        if (threadIdx.x == 0) *sh_flag = (any == 0u) ? 1 : 0;
    }
    __syncthreads();
    return *sh_flag;
}

__device__ __forceinline__ long long load_idx(const void* ei, size_t pos, int is64) {
    if (is64) return ((const long long*)ei)[pos];
    return (long long)((const int*)ei)[pos];
}

// ---------------------------------------------------------------------------
__global__ void mega_kernel(float4* __restrict__ out4,
                            float*  __restrict__ outf,
                            const void* __restrict__ ei,
                            const float4* __restrict__ attr,
                            const float* __restrict__ z,
                            const float* __restrict__ W,
                            const float* __restrict__ b) {
    __shared__ int sh_flag;
    int bid = blockIdx.x;

    if (bid < UV_BLOCKS) {
        // ---- u/v precompute ----
        int node = bid * 8 + (threadIdx.x >> 5);
        int lane = threadIdx.x & 31;
        if (node < N_NODES) {
            float4 zv = reinterpret_cast<const float4*>(z + (size_t)node * 128)[lane];
            float4 w1 = reinterpret_cast<const float4*>(W)[lane];
            float4 w2 = reinterpret_cast<const float4*>(W + 128)[lane];
            float s1 = zv.x * w1.x + zv.y * w1.y + zv.z * w1.z + zv.w * w1.w;
            float s2 = zv.x * w2.x + zv.y * w2.y + zv.z * w2.z + zv.w * w2.w;
            #pragma unroll
            for (int o = 16; o > 0; o >>= 1) {
                s1 += __shfl_xor_sync(0xFFFFFFFFu, s1, o);
                s2 += __shfl_xor_sync(0xFFFFFFFFu, s2, o);
            }
            if (lane == 0) {
                g_u[node] = s1 + b[0];
                g_v[node] = s2;
            }
        }
        __syncthreads();
        if (threadIdx.x == 0) {
            __threadfence();
            atomicAdd(&g_uv_done, 1u);
        }
    } else if (bid < UV_BLOCKS + EDGE_BLOCKS) {
        // ---- edge phase: hash insert + per-segment list append ----
        int is64 = block_detect_is64((const int*)ei, &sh_flag);
        int e = (bid - UV_BLOCKS) * 256 + threadIdx.x;

        long long r = 0, c = 0;
        bool valid = (e < N_EDGES);
        if (valid) {
            r = load_idx(ei, e, is64);
            c = load_idx(ei, (size_t)N_EDGES + e, is64);
            valid = ((unsigned long long)r < N_NODES) &&
                    ((unsigned long long)c < N_NODES);
        }
        float4 a = valid ? attr[e] : make_float4(0.f, 0.f, 0.f, 0.f);

        if (threadIdx.x == 0) {
            while (atomicAdd(&g_uv_done, 0u) < (unsigned)UV_BLOCKS) { }
            __threadfence();
        }
        __syncthreads();

        if (valid) {
            unsigned cell = (unsigned)(r * N_NODES + c);
            int key = (int)cell + 1;
            float add = a.x + a.y + a.z + a.w;

            unsigned h = ((unsigned)key * 2654435761u) >> (32 - HASH_BITS);
            while (true) {
                int prev = atomicCAS(&g_keys[h], 0, key);
                if (prev == 0) {                    // elected inserter
                    add += g_u[r] + g_v[c];
                    unsigned seg = cell >> SEG_SHIFT;
                    unsigned idx = atomicAdd(&g_seg_cnt[seg], 1u);
                    if (idx < SEG_CAP)
                        g_seg_list[seg * SEG_CAP + idx] = h;
                    // overflow (never for this dataset): slot stays occupied,
                    // handled by the tail sweep.
                    break;
                }
                if (prev == key) break;             // duplicate
                h = (h + 1u) & HASH_MASK;
            }
            atomicAdd(&g_vals[h], add);
        }
        __syncthreads();
        if (threadIdx.x == 0) {
            __threadfence();
            atomicAdd(&g_edge_done, 1u);
        }
    } else {
        // ---- zero + in-wave scatter: contiguous 128KB segment per block ----
        unsigned seg = (unsigned)(bid - UV_BLOCKS - EDGE_BLOCKS);   // < NSEG
        size_t base4 = (size_t)seg * SEG_F4;
        float4 zero = make_float4(0.f, 0.f, 0.f, 0.f);
        #pragma unroll 4
        for (int it = 0; it < SEG_F4 / 256; ++it)
            out4[base4 + (size_t)it * 256 + threadIdx.x] = zero;

        // wait for edge phase (in practice already done: zeros launch after
        // edge blocks exit; edges always terminate => no deadlock)
        if (threadIdx.x == 0) {
            while (atomicAdd(&g_edge_done, 0u) < (unsigned)EDGE_BLOCKS) { }
            __threadfence();
        }
        __syncthreads();

        unsigned cnt = g_seg_cnt[seg];
        if (cnt > SEG_CAP) cnt = SEG_CAP;
        for (unsigned j = threadIdx.x; j < cnt; j += 256) {
            unsigned slot = g_seg_list[seg * SEG_CAP + j];
            int k = g_keys[slot];
            outf[(size_t)(unsigned)(k - 1)] = g_vals[slot];  // segment L2-hot
            g_keys[slot] = 0;                                // self-clean
            g_vals[slot] = 0.0f;
        }
        if (threadIdx.x == 0) g_seg_cnt[seg] = 0;
    }
}

// ---------------------------------------------------------------------------
// Tail: safety sweep (CAP-overflow slots only; none in practice) + re-arm.
// ---------------------------------------------------------------------------
__global__ void tail_kernel(float* __restrict__ out) {
    unsigned t = blockIdx.x * 256u + threadIdx.x;
    if (t == 0) { g_uv_done = 0; g_edge_done = 0; }
    if (t >= HASH_SIZE) return;
    int k = g_keys[t];
    if (k > 0) {
        out[(size_t)(unsigned)(k - 1)] = g_vals[t];
        g_keys[t] = 0;
        g_vals[t] = 0.0f;
    }
}

// ---------------------------------------------------------------------------
extern "C" void kernel_launch(void* const* d_in, const int* in_sizes, int n_in,
                              void* d_out, int out_size) {
    const float*  z    = (const float*)d_in[0];
    const void*   ei   = d_in[1];
    const float4* attr = (const float4*)d_in[2];
    const float*  W    = (const float*)d_in[3];
    const float*  b    = (const float*)d_in[4];
    float*        out  = (float*)d_out;

    mega_kernel<<<UV_BLOCKS + EDGE_BLOCKS + NSEG, 256>>>(
        (float4*)out, out, ei, attr, z, W, b);
    tail_kernel<<<(HASH_SIZE + 255) / 256, 256>>>(out);
}

// round 13
// speedup vs baseline: 1.2819x; 1.2819x over previous
#include <cuda_runtime.h>
#include <cuda_bf16.h>
#include <cstdint>

// Inputs (metadata order):
//   d_in[0] = z          float32 [12288, 128]
//   d_in[1] = edge_index int32 [2, 393216] (jnp.int64 silently downcast; detect)
//   d_in[2] = edge_attr  float32 [393216, 4]
//   d_in[3] = W          float32 [1, 256]
//   d_in[4] = b          float32 [1]
// Output: float32 [12288, 12288]
//
// out[r,c] = sum_dup(attr_sum) + (u[r]+v[c]+b) once per distinct cell.
// R8 skeleton (measured best) + ORDER-PRESERVING hash:
//   slot0(cell) = cell * 2^20 / 151M  (monotonic multiply-shift)
// so the scatter's sequential slot sweep emits output stores in ascending
// address order -> sequential DRAM row activation instead of random, at zero
// extra cost. Hash self-cleaning (0 = empty, scatter restores slots).

#define N_NODES 12288
#define N_EDGES 393216

#define UV_BLOCKS    1536   // 8 warps/block -> 12288 warps, one per node
#define EDGE_BLOCKS  1536   // thread per edge
#define ZERO_BLOCKS  4736   // 148 SMs * 32

#define HASH_BITS 20
#define HASH_SIZE (1u << HASH_BITS)         // 1,048,576 slots (load ~0.37)
#define HASH_MASK (HASH_SIZE - 1u)
// floor(2^32 * HASH_SIZE / (N_NODES*N_NODES)) = floor(2^52 / 150994944)
#define HASH_MULT 29826161ull

__device__ int   g_keys[HASH_SIZE];         // cell+1, 0 = empty; zero-init
__device__ float g_vals[HASH_SIZE];         // accumulated value; zero-init
__device__ float g_u[N_NODES];              // dot(z[i], W[0:128]) + b
__device__ float g_v[N_NODES];              // dot(z[i], W[128:256])

// ---------------------------------------------------------------------------
__device__ __forceinline__ int block_detect_is64(const int* __restrict__ ei32,
                                                 int* sh_flag) {
    if (threadIdx.x < 32) {
        int w = ei32[2 * threadIdx.x + 1];
        unsigned any = __ballot_sync(0xFFFFFFFFu, w != 0);
        if (threadIdx.x == 0) *sh_flag = (any == 0u) ? 1 : 0;
    }
    __syncthreads();
    return *sh_flag;
}

__device__ __forceinline__ long long load_idx(const void* ei, size_t pos, int is64) {
    if (is64) return ((const long long*)ei)[pos];
    return (long long)((const int*)ei)[pos];
}

// order-preserving initial slot: cell/144 scaled into [0, HASH_SIZE)
__device__ __forceinline__ unsigned hash_slot(unsigned cell) {
    return (unsigned)(((unsigned long long)cell * HASH_MULT) >> 32);
}

// ---------------------------------------------------------------------------
// Kernel 1: u/v precompute (warp-per-node dot; bias folded into u).
// ---------------------------------------------------------------------------
__global__ void init_kernel(const float* __restrict__ z,
                            const float* __restrict__ W,
                            const float* __restrict__ b) {
    int node = blockIdx.x * 8 + (threadIdx.x >> 5);
    int lane = threadIdx.x & 31;
    if (node >= N_NODES) return;
    float4 zv = reinterpret_cast<const float4*>(z + (size_t)node * 128)[lane];
    float4 w1 = reinterpret_cast<const float4*>(W)[lane];
    float4 w2 = reinterpret_cast<const float4*>(W + 128)[lane];
    float s1 = zv.x * w1.x + zv.y * w1.y + zv.z * w1.z + zv.w * w1.w;
    float s2 = zv.x * w2.x + zv.y * w2.y + zv.z * w2.z + zv.w * w2.w;
    #pragma unroll
    for (int o = 16; o > 0; o >>= 1) {
        s1 += __shfl_xor_sync(0xFFFFFFFFu, s1, o);
        s2 += __shfl_xor_sync(0xFFFFFFFFu, s2, o);
    }
    if (lane == 0) {
        g_u[node] = s1 + b[0];
        g_v[node] = s2;
    }
}

// ---------------------------------------------------------------------------
// Kernel 2: mega. Edge blocks FIRST (hide under zero stream), no spins:
//   [0, EDGE)   : hash-insert cell+1 (atomicCAS election) + atomicAdd value
//   [EDGE, ...) : zero out, grid-stride float4 (validated floor pattern)
// ---------------------------------------------------------------------------
__global__ void mega_kernel(float4* __restrict__ out, size_t n4,
                            const void* __restrict__ ei,
                            const float4* __restrict__ attr) {
    __shared__ int sh_flag;
    int bid = blockIdx.x;

    if (bid < EDGE_BLOCKS) {
        int is64 = block_detect_is64((const int*)ei, &sh_flag);
        int e = bid * 256 + threadIdx.x;
        if (e >= N_EDGES) return;
        long long r = load_idx(ei, e, is64);
        long long c = load_idx(ei, (size_t)N_EDGES + e, is64);
        if ((unsigned long long)r >= N_NODES || (unsigned long long)c >= N_NODES) return;

        float4 a = attr[e];
        unsigned cell = (unsigned)(r * N_NODES + c);
        int key = (int)cell + 1;                    // 0 reserved for empty
        float add = a.x + a.y + a.z + a.w;

        unsigned h = hash_slot(cell);
        while (true) {
            int prev = atomicCAS(&g_keys[h], 0, key);
            if (prev == 0)  { add += g_u[r] + g_v[c]; break; }   // elected
            if (prev == key) break;                              // duplicate
            h = (h + 1u) & HASH_MASK;
        }
        atomicAdd(&g_vals[h], add);
    } else {
        size_t i = (size_t)(bid - EDGE_BLOCKS) * blockDim.x + threadIdx.x;
        size_t stride = (size_t)ZERO_BLOCKS * blockDim.x;
        float4 zero = make_float4(0.f, 0.f, 0.f, 0.f);
        for (; i < n4; i += stride) out[i] = zero;
    }
}

// ---------------------------------------------------------------------------
// Kernel 3: scatter hash -> out. Sequential slot sweep; because the hash is
// order-preserving, out stores ascend in address => sequential DRAM rows.
// Restores slots to empty (self-cleaning, graph-safe).
// ---------------------------------------------------------------------------
__global__ void scatter_kernel(float* __restrict__ out) {
    unsigned t = blockIdx.x * 256u + threadIdx.x;
    if (t >= HASH_SIZE) return;
    int k = g_keys[t];
    if (k > 0) {
        out[(size_t)(unsigned)(k - 1)] = g_vals[t];
        g_keys[t] = 0;
        g_vals[t] = 0.0f;
    }
}

// ---------------------------------------------------------------------------
extern "C" void kernel_launch(void* const* d_in, const int* in_sizes, int n_in,
                              void* d_out, int out_size) {
    const float*  z    = (const float*)d_in[0];
    const void*   ei   = d_in[1];
    const float4* attr = (const float4*)d_in[2];
    const float*  W    = (const float*)d_in[3];
    const float*  b    = (const float*)d_in[4];
    float*        out  = (float*)d_out;

    size_t n4 = (size_t)out_size / 4;

    init_kernel<<<UV_BLOCKS, 256>>>(z, W, b);
    mega_kernel<<<EDGE_BLOCKS + ZERO_BLOCKS, 256>>>((float4*)out, n4, ei, attr);
    scatter_kernel<<<(HASH_SIZE + 255) / 256, 256>>>(out);
}